// round 5
// baseline (speedup 1.0000x reference)
#include <cuda_runtime.h>

#define ALPHA_F 0.1f

constexpr int Bb  = 32;
constexpr int Tt  = 2048;
constexpr int DIN = 128;
constexpr int Hh  = 512;

// Scratch for x_proj_scaled = ALPHA * x @ I^T : [B*T, H] fp32 (128 MB)
__device__ float g_xproj[(size_t)Bb * Tt * Hh];

// ---------------- packed-f32x2 helpers (FFMA2 path, 2x fp32 rate) ----------
#define PACK2(d, lo, hi)   asm("mov.b64 %0, {%1, %2};" : "=l"(d) : "f"(lo), "f"(hi))
#define UNPACK2(lo, hi, s) asm("mov.b64 {%0, %1}, %2;" : "=f"(lo), "=f"(hi) : "l"(s))
#define FMA2(d, a, b)      asm("fma.rn.f32x2 %0, %1, %2, %0;" : "+l"(d) : "l"(a), "l"(b))
#define FMA2A(d, a, b, c)  asm("fma.rn.f32x2 %0, %1, %2, %3;" : "=l"(d) : "l"(a), "l"(b), "l"(c))
#define ADD2(d, a, b)      asm("add.rn.f32x2 %0, %1, %2;" : "=l"(d) : "l"(a), "l"(b))

// =====================================================================
// Kernel 1: x_proj[m][h] = ALPHA * sum_d x[m][d] * I[h][d]  (NT GEMM, K=128)
// 128x128x32 tiles, 8x8 microtile per thread, FFMA2 inner product.
// ALPHA folded here so the scan consumes xp with zero extra flops.
// =====================================================================
constexpr int BM = 128, BN = 128, BK = 32;

__global__ __launch_bounds__(256, 2) void proj_kernel(const float* __restrict__ X,
                                                      const float* __restrict__ Iw) {
    __shared__ float As[BK][BM + 4];
    __shared__ float Bs[BK][BN + 4];
    const int tid = threadIdx.x;
    const int tx  = tid & 15;   // N microtile index
    const int ty  = tid >> 4;   // M microtile index
    const long long m0 = (long long)blockIdx.y * BM;
    const int       n0 = blockIdx.x * BN;

    unsigned long long acc[8][4];
#pragma unroll
    for (int i = 0; i < 8; i++)
#pragma unroll
        for (int j = 0; j < 4; j++) acc[i][j] = 0ull;

    for (int kt = 0; kt < DIN; kt += BK) {
#pragma unroll
        for (int q = 0; q < 4; q++) {
            int p   = tid + q * 256;   // 0..1023 float4 slots
            int row = p >> 3;          // 0..127
            int kq  = p & 7;           // 0..7 (k quad)
            float4 av = *(const float4*)(X + (m0 + row) * DIN + kt + kq * 4);
            As[kq * 4 + 0][row] = av.x; As[kq * 4 + 1][row] = av.y;
            As[kq * 4 + 2][row] = av.z; As[kq * 4 + 3][row] = av.w;
            float4 bv = *(const float4*)(Iw + (long long)(n0 + row) * DIN + kt + kq * 4);
            // fold ALPHA into the I operand
            Bs[kq * 4 + 0][row] = ALPHA_F * bv.x; Bs[kq * 4 + 1][row] = ALPHA_F * bv.y;
            Bs[kq * 4 + 2][row] = ALPHA_F * bv.z; Bs[kq * 4 + 3][row] = ALPHA_F * bv.w;
        }
        __syncthreads();

#pragma unroll
        for (int k = 0; k < BK; k++) {
            float4 a0 = *(const float4*)&As[k][ty * 8];
            float4 a1 = *(const float4*)&As[k][ty * 8 + 4];
            const unsigned long long* bp =
                (const unsigned long long*)&Bs[k][tx * 8];
            unsigned long long pb0 = bp[0], pb1 = bp[1], pb2 = bp[2], pb3 = bp[3];
            float av[8] = {a0.x, a0.y, a0.z, a0.w, a1.x, a1.y, a1.z, a1.w};
#pragma unroll
            for (int i = 0; i < 8; i++) {
                unsigned long long pa;
                PACK2(pa, av[i], av[i]);
                FMA2(acc[i][0], pa, pb0);
                FMA2(acc[i][1], pa, pb1);
                FMA2(acc[i][2], pa, pb2);
                FMA2(acc[i][3], pa, pb3);
            }
        }
        __syncthreads();
    }

#pragma unroll
    for (int i = 0; i < 8; i++) {
        float4 o0, o1;
        UNPACK2(o0.x, o0.y, acc[i][0]);
        UNPACK2(o0.z, o0.w, acc[i][1]);
        UNPACK2(o1.x, o1.y, acc[i][2]);
        UNPACK2(o1.z, o1.w, acc[i][3]);
        long long row = m0 + ty * 8 + i;
        float* op = g_xproj + row * Hh + n0 + tx * 8;
        *(float4*)op       = o0;
        *(float4*)(op + 4) = o1;
    }
}

// =====================================================================
// Kernel 2: sequential scan. ONE WARP per batch, 16 h per thread.
// Warp-level REDUX gives the complete rank-2 coupling (S0, S1):
// no smem exchange, no bar.sync, no cross-warp combine.
//  - h kept as 8 packed f32x2; dot + update in FFMA2
//  - fixed-point warp reduce (x2^23 -> s32 REDUX.SUM -> I2F)
//  - out[t-1] stored + prefetch LDGs issued inside the REDUX shadow
//  - 2-deep prefetch ring (8 LDG.128 in flight)
// =====================================================================
__device__ __forceinline__ float tanh_fast(float x) {
    float y;
    asm("tanh.approx.f32 %0, %1;" : "=f"(y) : "f"(x));
    return y;
}

constexpr float FXSCALE = 8388608.0f;        // 2^23
constexpr float FXINV   = 1.0f / 8388608.0f;

__global__ __launch_bounds__(32, 1) void scan_kernel(const float* __restrict__ mw,
                                                     const float* __restrict__ nw,
                                                     float* __restrict__ out) {
    const int b    = blockIdx.x;
    const int lane = threadIdx.x;
    const int i0   = lane * 16;          // first h index owned by this thread

    // ---- constants in registers ----
    unsigned long long n01p[16];         // (2^23*n0[j], 2^23*n1[j])
#pragma unroll
    for (int j = 0; j < 16; j++) {
        float a = FXSCALE * nw[(i0 + j) * 2 + 0];
        float c = FXSCALE * nw[(i0 + j) * 2 + 1];
        PACK2(n01p[j], a, c);
    }
    unsigned long long am0p[8], am1p[8]; // (alpha*m/2^23) for the h-pair halves
#pragma unroll
    for (int p = 0; p < 8; p++) {
        float a0 = (ALPHA_F * FXINV) * mw[(i0 + 2 * p) * 2 + 0];
        float a1 = (ALPHA_F * FXINV) * mw[(i0 + 2 * p + 1) * 2 + 0];
        PACK2(am0p[p], a0, a1);
        float b0 = (ALPHA_F * FXINV) * mw[(i0 + 2 * p) * 2 + 1];
        float b1 = (ALPHA_F * FXINV) * mw[(i0 + 2 * p + 1) * 2 + 1];
        PACK2(am1p[p], b0, b1);
    }
    unsigned long long DEC;
    PACK2(DEC, 1.0f - ALPHA_F, 1.0f - ALPHA_F);

    unsigned long long h[8];
#pragma unroll
    for (int p = 0; p < 8; p++) h[p] = 0ull;

    const float4* xpb = (const float4*)(g_xproj + (size_t)b * Tt * Hh);
    float*        outb = out + (size_t)b * Tt * Hh + i0;
    const int ROW4 = Hh / 4;             // float4 per timestep row

    // 2-deep prefetch ring: 4 float4 per step per thread
    float4 ring[2][4];
#pragma unroll
    for (int s = 0; s < 2; s++)
#pragma unroll
        for (int q = 0; q < 4; q++)
            ring[s][q] = xpb[(size_t)s * ROW4 + lane * 4 + q];

#pragma unroll 2
    for (int t = 0; t < Tt; t++) {
        const int slot = t & 1;

        // ---- tanh of all 16 h ----
        float th[16];
#pragma unroll
        for (int p = 0; p < 8; p++) {
            float lo, hi;
            UNPACK2(lo, hi, h[p]);
            th[2 * p]     = tanh_fast(lo);
            th[2 * p + 1] = tanh_fast(hi);
        }

        // ---- packed dot: (s0, s1) jointly, 4 chains then tree-combine ----
        unsigned long long a0 = 0ull, a1 = 0ull, a2 = 0ull, a3 = 0ull;
#pragma unroll
        for (int j = 0; j < 4; j++) {
            unsigned long long d;
            PACK2(d, th[j], th[j]);           FMA2(a0, d, n01p[j]);
            PACK2(d, th[j + 4], th[j + 4]);   FMA2(a1, d, n01p[j + 4]);
            PACK2(d, th[j + 8], th[j + 8]);   FMA2(a2, d, n01p[j + 8]);
            PACK2(d, th[j + 12], th[j + 12]); FMA2(a3, d, n01p[j + 12]);
        }
        ADD2(a0, a0, a1);
        ADD2(a2, a2, a3);
        ADD2(a0, a0, a2);
        float s0f, s1f;
        UNPACK2(s0f, s1f, a0);

        int S0i = __reduce_add_sync(0xffffffffu, __float2int_rn(s0f));
        int S1i = __reduce_add_sync(0xffffffffu, __float2int_rn(s1f));

        // ---- REDUX shadow: store out[t-1] (h regs still hold h_{t}) ----
        if (t > 0) {
            float* o = outb + (size_t)(t - 1) * Hh;
#pragma unroll
            for (int q = 0; q < 4; q++)
                *(ulonglong2*)(o + q * 4) = make_ulonglong2(h[2 * q], h[2 * q + 1]);
        }
        // consume + refill prefetch ring (also in the shadow)
        float4 xpv[4];
#pragma unroll
        for (int q = 0; q < 4; q++) xpv[q] = ring[slot][q];
        {
            int tp = t + 2 < Tt ? t + 2 : Tt - 1;
#pragma unroll
            for (int q = 0; q < 4; q++)
                ring[slot][q] = xpb[(size_t)tp * ROW4 + lane * 4 + q];
        }

        float S0 = (float)S0i, S1 = (float)S1i;
        unsigned long long S0d, S1d;
        PACK2(S0d, S0, S0);
        PACK2(S1d, S1, S1);

        // ---- packed update: h = 0.9*h + am0*S0 + am1*S1 + xp ----
#pragma unroll
        for (int p = 0; p < 8; p++) {
            unsigned long long xpp;
            float xlo = (p & 1) ? xpv[p >> 1].z : xpv[p >> 1].x;
            float xhi = (p & 1) ? xpv[p >> 1].w : xpv[p >> 1].y;
            PACK2(xpp, xlo, xhi);
            unsigned long long t2;
            FMA2A(t2, am1p[p], S1d, xpp);
            FMA2A(t2, am0p[p], S0d, t2);
            FMA2A(h[p], h[p], DEC, t2);
        }
    }

    // final output row
    float* o = outb + (size_t)(Tt - 1) * Hh;
#pragma unroll
    for (int q = 0; q < 4; q++)
        *(ulonglong2*)(o + q * 4) = make_ulonglong2(h[2 * q], h[2 * q + 1]);
}

// =====================================================================
extern "C" void kernel_launch(void* const* d_in, const int* in_sizes, int n_in,
                              void* d_out, int out_size) {
    const float* x  = (const float*)d_in[0];  // [32, 2048, 128]
    const float* m  = (const float*)d_in[1];  // [512, 2]
    const float* n  = (const float*)d_in[2];  // [512, 2]
    const float* Iw = (const float*)d_in[3];  // [512, 128]
    float* out = (float*)d_out;               // [32, 2048, 512]

    dim3 pg(Hh / BN, (Bb * Tt) / BM);  // (4, 512)
    proj_kernel<<<pg, 256>>>(x, Iw);
    scan_kernel<<<Bb, 32>>>(m, n, out);
}

// round 6
// speedup vs baseline: 1.9054x; 1.9054x over previous
#include <cuda_runtime.h>

#define ALPHA_F 0.1f

constexpr int Bb  = 32;
constexpr int Tt  = 2048;
constexpr int DIN = 128;
constexpr int Hh  = 512;
constexpr int CHUNK = 128;                 // timesteps per proj M-tile
constexpr int NCH  = Tt / CHUNK;           // 16 chunks per batch

// Scratch for x_proj_scaled = ALPHA * x @ I^T : [B*T, H] fp32 (128 MB)
__device__ float g_xproj[(size_t)Bb * Tt * Hh];
// Per (batch, chunk) completion counters (4 N-tiles each)
__device__ int g_cnt[Bb][NCH];

// ---------------- packed-f32x2 helpers ----------
#define PACK2(d, lo, hi)   asm("mov.b64 %0, {%1, %2};" : "=l"(d) : "f"(lo), "f"(hi))
#define UNPACK2(lo, hi, s) asm("mov.b64 {%0, %1}, %2;" : "=f"(lo), "=f"(hi) : "l"(s))
#define FMA2(d, a, b)      asm("fma.rn.f32x2 %0, %1, %2, %0;" : "+l"(d) : "l"(a), "l"(b))

__device__ __forceinline__ float tanh_fast(float x) {
    float y;
    asm("tanh.approx.f32 %0, %1;" : "=f"(y) : "f"(x));
    return y;
}

constexpr float FXSCALE = 8388608.0f;        // 2^23
constexpr float FXINV   = 1.0f / 8388608.0f;

constexpr int BM = 128, BN = 128, BK = 32;

__global__ void zero_cnt_kernel() {
    int i = threadIdx.x;
    if (i < Bb * NCH) ((int*)g_cnt)[i] = 0;
}

// consumer-side gate: wait until all 4 N-tiles of (b, chunk) are written
__device__ __forceinline__ void wait_chunk(int b, int c) {
    volatile int* p = &g_cnt[b][c];
    if (*p < 4) {
        while (*p < 4) __nanosleep(64);
    }
    __threadfence();   // acquire
}

// =====================================================================
// Fused kernel.
//  blocks [0,32):   scan, one batch each, 128 active threads (R3 layout)
//  blocks [32,2080): proj tiles, ordered chunk-major then batch so early
//                    timesteps across all batches complete first.
// =====================================================================
__global__ __launch_bounds__(256, 2) void fused_kernel(const float* __restrict__ X,
                                                       const float* __restrict__ Iw,
                                                       const float* __restrict__ mw,
                                                       const float* __restrict__ nw,
                                                       float* __restrict__ out) {
    __shared__ float As[BK][BM + 4];
    __shared__ float Bs[BK][BN + 4];
    __shared__ int4  wsum[2][2];

    const int bid = blockIdx.x;

    if (bid >= Bb) {
        // ================= PROJ TILE =================
        const int pbid = bid - Bb;           // 0..2047
        const int tc   = pbid >> 7;          // chunk 0..15
        const int rem  = pbid & 127;
        const int b    = rem >> 2;           // batch 0..31
        const int nc   = rem & 3;            // N tile 0..3
        const long long m0 = (long long)b * Tt + (long long)tc * CHUNK;
        const int       n0 = nc * BN;

        const int tid = threadIdx.x;
        const int tx  = tid & 15;
        const int ty  = tid >> 4;

        unsigned long long acc[8][4];
#pragma unroll
        for (int i = 0; i < 8; i++)
#pragma unroll
            for (int j = 0; j < 4; j++) acc[i][j] = 0ull;

        for (int kt = 0; kt < DIN; kt += BK) {
#pragma unroll
            for (int q = 0; q < 4; q++) {
                int p   = tid + q * 256;
                int row = p >> 3;
                int kq  = p & 7;
                float4 av = *(const float4*)(X + (m0 + row) * DIN + kt + kq * 4);
                As[kq * 4 + 0][row] = av.x; As[kq * 4 + 1][row] = av.y;
                As[kq * 4 + 2][row] = av.z; As[kq * 4 + 3][row] = av.w;
                float4 bv = *(const float4*)(Iw + (long long)(n0 + row) * DIN + kt + kq * 4);
                // fold ALPHA into the I operand
                Bs[kq * 4 + 0][row] = ALPHA_F * bv.x; Bs[kq * 4 + 1][row] = ALPHA_F * bv.y;
                Bs[kq * 4 + 2][row] = ALPHA_F * bv.z; Bs[kq * 4 + 3][row] = ALPHA_F * bv.w;
            }
            __syncthreads();

#pragma unroll
            for (int k = 0; k < BK; k++) {
                float4 a0 = *(const float4*)&As[k][ty * 8];
                float4 a1 = *(const float4*)&As[k][ty * 8 + 4];
                const unsigned long long* bp =
                    (const unsigned long long*)&Bs[k][tx * 8];
                unsigned long long pb0 = bp[0], pb1 = bp[1], pb2 = bp[2], pb3 = bp[3];
                float av[8] = {a0.x, a0.y, a0.z, a0.w, a1.x, a1.y, a1.z, a1.w};
#pragma unroll
                for (int i = 0; i < 8; i++) {
                    unsigned long long pa;
                    PACK2(pa, av[i], av[i]);
                    FMA2(acc[i][0], pa, pb0);
                    FMA2(acc[i][1], pa, pb1);
                    FMA2(acc[i][2], pa, pb2);
                    FMA2(acc[i][3], pa, pb3);
                }
            }
            __syncthreads();
        }

#pragma unroll
        for (int i = 0; i < 8; i++) {
            float4 o0, o1;
            UNPACK2(o0.x, o0.y, acc[i][0]);
            UNPACK2(o0.z, o0.w, acc[i][1]);
            UNPACK2(o1.x, o1.y, acc[i][2]);
            UNPACK2(o1.z, o1.w, acc[i][3]);
            long long row = m0 + ty * 8 + i;
            float* op = g_xproj + row * Hh + n0 + tx * 8;
            *(float4*)op       = o0;
            *(float4*)(op + 4) = o1;
        }

        // publish: all writes visible, then bump (b, tc) counter
        __threadfence();
        __syncthreads();
        if (tid == 0) atomicAdd(&g_cnt[b][tc], 1);
        return;
    }

    // ================= SCAN =================
    if (threadIdx.x >= 128) return;   // 128 active threads

    const int b    = bid;
    const int tid  = threadIdx.x;
    const int wid  = tid >> 5;
    const int lane = tid & 31;

    float h0v = 0.f, h1v = 0.f, h2v = 0.f, h3v = 0.f;
    const int i0 = tid * 4;
    float am0[4], am1[4], n0[4], n1[4];
#pragma unroll
    for (int j = 0; j < 4; j++) {
        am0[j] = (ALPHA_F * FXINV) * mw[(i0 + j) * 2 + 0];
        am1[j] = (ALPHA_F * FXINV) * mw[(i0 + j) * 2 + 1];
        n0[j]  = FXSCALE * nw[(i0 + j) * 2 + 0];
        n1[j]  = FXSCALE * nw[(i0 + j) * 2 + 1];
    }
    const float4* xp4  = (const float4*)(g_xproj + (size_t)b * Tt * Hh);
    float*        outb = out + (size_t)b * Tt * Hh;

    // first chunk must be ready before the initial ring fill
    wait_chunk(b, 0);

    // 4-deep prefetch ring
    float4 ring[4];
#pragma unroll
    for (int j = 0; j < 4; j++) ring[j] = xp4[(size_t)j * (Hh / 4) + tid];

#pragma unroll 4
    for (int t = 0; t < Tt; t++) {
        const int slot = t & 3;
        float4 xp = ring[slot];
        {
            int tp = t + 4;
            if (tp < Tt) {
                if ((tp & (CHUNK - 1)) == 0) wait_chunk(b, tp >> 7);
            } else {
                tp = Tt - 1;
            }
            ring[slot] = xp4[(size_t)tp * (Hh / 4) + tid];
        }

        // -- critical path: tanh -> local dot (pre-scaled) -> f2i -> REDUX --
        float th0 = tanh_fast(h0v), th1 = tanh_fast(h1v);
        float th2 = tanh_fast(h2v), th3 = tanh_fast(h3v);
        float s0f = fmaf(th0, n0[0], th1 * n0[1]) + fmaf(th2, n0[2], th3 * n0[3]);
        float s1f = fmaf(th0, n1[0], th1 * n1[1]) + fmaf(th2, n1[2], th3 * n1[3]);
        int s0 = __reduce_add_sync(0xffffffffu, __float2int_rn(s0f));
        int s1 = __reduce_add_sync(0xffffffffu, __float2int_rn(s1f));

        const int buf = t & 1;
        if (lane == 0) {
            int* w = (int*)&wsum[buf][0];
            w[wid * 2 + 0] = s0;
            w[wid * 2 + 1] = s1;
        }
        __syncthreads();
        int4 p0 = wsum[buf][0];
        int4 p1 = wsum[buf][1];
        float S0 = (float)((p0.x + p0.z) + (p1.x + p1.z));  // still x2^23
        float S1 = (float)((p0.y + p0.w) + (p1.y + p1.w));

        // h = 0.9*h + (a*m0/2^23)S0 + (a*m1/2^23)S1 + xp   (xp pre-scaled by a)
        h0v = fmaf(h0v, 1.0f - ALPHA_F, fmaf(am0[0], S0, fmaf(am1[0], S1, xp.x)));
        h1v = fmaf(h1v, 1.0f - ALPHA_F, fmaf(am0[1], S0, fmaf(am1[1], S1, xp.y)));
        h2v = fmaf(h2v, 1.0f - ALPHA_F, fmaf(am0[2], S0, fmaf(am1[2], S1, xp.z)));
        h3v = fmaf(h3v, 1.0f - ALPHA_F, fmaf(am0[3], S0, fmaf(am1[3], S1, xp.w)));

        *(float4*)&outb[(size_t)t * Hh + i0] = make_float4(h0v, h1v, h2v, h3v);
    }
}

// =====================================================================
extern "C" void kernel_launch(void* const* d_in, const int* in_sizes, int n_in,
                              void* d_out, int out_size) {
    const float* x  = (const float*)d_in[0];  // [32, 2048, 128]
    const float* m  = (const float*)d_in[1];  // [512, 2]
    const float* n  = (const float*)d_in[2];  // [512, 2]
    const float* Iw = (const float*)d_in[3];  // [512, 128]
    float* out = (float*)d_out;               // [32, 2048, 512]

    zero_cnt_kernel<<<1, 512>>>();
    fused_kernel<<<Bb + (Bb * NCH * 4), 256>>>(x, Iw, m, n, out);
}